// round 9
// baseline (speedup 1.0000x reference)
#include <cuda_runtime.h>

// ---------------------------------------------------------------------------
// Compile-time Clebsch-Gordan coefficients (Racah formula), matching numpy ref.
// ---------------------------------------------------------------------------

__host__ __device__ constexpr double cfact(int n) {
    double r = 1.0;
    for (int i = 2; i <= n; ++i) r *= (double)i;
    return r;
}

__host__ __device__ constexpr double csqrt_(double x) {
    if (x <= 0.0) return 0.0;
    double g = x > 1.0 ? x : 1.0;
    for (int i = 0; i < 100; ++i) g = 0.5 * (g + x / g);
    return g;
}

__host__ __device__ constexpr double cg_elem(int l1, int l2, int L, int m1, int m2) {
    const int M = m1 + m2;
    if (M < -L || M > L) return 0.0;
    const double pref0 = csqrt_((2.0 * L + 1.0) * cfact(L + l1 - l2) * cfact(L - l1 + l2) *
                                cfact(l1 + l2 - L) / cfact(l1 + l2 + L + 1));
    const double pref = pref0 * csqrt_(cfact(L + M) * cfact(L - M) * cfact(l1 - m1) *
                                       cfact(l1 + m1) * cfact(l2 - m2) * cfact(l2 + m2));
    double s = 0.0;
    for (int k = 0; k <= l1 + l2 - L; ++k) {
        if (l1 - m1 - k < 0 || l2 + m2 - k < 0 || L - l2 + m1 + k < 0 || L - l1 - m2 + k < 0)
            continue;
        const double d = cfact(k) * cfact(l1 + l2 - L - k) * cfact(l1 - m1 - k) *
                         cfact(l2 + m2 - k) * cfact(L - l2 + m1 + k) * cfact(L - l1 - m2 + k);
        s += ((k & 1) ? -1.0 : 1.0) / d;
    }
    return pref * s;
}

__host__ __device__ constexpr bool cg_nz(double c) { return c > 1e-12 || c < -1e-12; }

__host__ __device__ constexpr bool okL(int l1, int l2, int L, int a, int b) {
    const int off = l1 + l2 - L;
    const int mu = a + b - off;
    return mu >= 0 && mu <= 2 * L && cg_nz(cg_elem(l1, l2, L, a - l1, b - l2));
}

__host__ __device__ constexpr bool pair_any(int l1, int l2, int Lmin, int Lmax,
                                            int p, int q, int m, int n) {
    for (int L = Lmin; L <= Lmax; ++L)
        if (okL(l1, l2, L, m, n) && okL(l1, l2, L, p, q)) return true;
    return false;
}

__host__ __device__ constexpr bool col_any_p(int l1, int l2, int Lmin, int Lmax, int p, int q) {
    for (int L = Lmin; L <= Lmax; ++L)
        if (okL(l1, l2, L, p, q)) return true;
    return false;
}

__host__ __device__ constexpr bool col_any_q(int l1, int l2, int Lmin, int Lmax, int q, bool sym) {
    const int pmax = sym ? q : 2 * l1;
    for (int p = 0; p <= pmax; ++p)
        if (col_any_p(l1, l2, Lmin, Lmax, p, q)) return true;
    return false;
}

__host__ __device__ constexpr bool row_any(int l1, int l2, int Lmin, int Lmax,
                                           int p, int q, int m, int nlo) {
    for (int nn = nlo; nn <= 2 * l2; ++nn)
        if (pair_any(l1, l2, Lmin, Lmax, p, q, m, nn)) return true;
    return false;
}

// ---------------------------------------------------------------------------
// Packed f32x2 helpers (sm_100+): FMUL2 does 2 products per instruction.
// ptxas will NOT auto-fuse these — hand-written PTX required.
// ---------------------------------------------------------------------------

__device__ __forceinline__ unsigned long long pack2(float lo, float hi) {
    unsigned long long r;
    asm("mov.b64 %0, {%1, %2};" : "=l"(r) : "f"(lo), "f"(hi));
    return r;
}

__device__ __forceinline__ unsigned long long mul2(unsigned long long a, unsigned long long b) {
    unsigned long long r;
    asm("mul.rn.f32x2 %0, %1, %2;" : "=l"(r) : "l"(a), "l"(b));
    return r;
}

__device__ __forceinline__ void unpack2(unsigned long long v, float& lo, float& hi) {
    asm("mov.b64 {%0, %1}, %2;" : "=f"(lo), "=f"(hi) : "l"(v));
}

// ---------------------------------------------------------------------------
// Smem operand wrapper (linear layout: this thread's matrix at p[0..d*d)).
// ---------------------------------------------------------------------------

struct SmemMat {
    const float* p;
    template <int I> __device__ __forceinline__ float at() const { return p[I]; }
};

template <int d, int col, class M, int i = 0>
__device__ __forceinline__ void load_col(const M& mat, float (&dst)[d]) {
    if constexpr (i < d) {
        dst[i] = mat.template at<i * d + col>();
        load_col<d, col, M, i + 1>(mat, dst);
    }
}

// pack adjacent pairs (2k,2k+1) of a column; unused entries are DCE'd
template <int d, int k = 0>
__device__ __forceinline__ void pack_pairs(const float (&b)[d], unsigned long long (&b2)[d / 2]) {
    if constexpr (k < d / 2) {
        b2[k] = pack2(b[2 * k], b[2 * k + 1]);
        pack_pairs<d, k + 1>(b, b2);
    }
}

// ---------------------------------------------------------------------------
// Accumulator group (each pass touches only a subset; SROA drops the rest)
// ---------------------------------------------------------------------------

struct EAcc {
    float e0[1];
    float e1[9];
    float e2[25];
    float e3[49];
};

template <int L> __device__ __forceinline__ auto& getE(EAcc& a) {
    if constexpr (L == 0) return a.e0;
    else if constexpr (L == 1) return a.e1;
    else if constexpr (L == 2) return a.e2;
    else return a.e3;
}

template <int N>
__device__ __forceinline__ void zeroa(float (&e)[N]) {
#pragma unroll
    for (int i = 0; i < N; ++i) e[i] = 0.f;
}

// ---------------------------------------------------------------------------
// CG scatter: one product feeds an FFMA-imm per valid L.
// ---------------------------------------------------------------------------

template <int l1, int l2, int p, int q, int m, int n, int W, int L, int Lmax>
__device__ __forceinline__ void l_scatter(float prod, EAcc& acc) {
    if constexpr (L <= Lmax) {
        if constexpr (okL(l1, l2, L, m, n) && okL(l1, l2, L, p, q)) {
            constexpr int off = l1 + l2 - L, DL = 2 * L + 1;
            constexpr int mu = m + n - off, nu = p + q - off;
            constexpr float w = (float)((double)W * cg_elem(l1, l2, L, m - l1, n - l2) *
                                        cg_elem(l1, l2, L, p - l1, q - l2));
            getE<L>(acc)[mu * DL + nu] = __fmaf_rn(w, prod, getE<L>(acc)[mu * DL + nu]);
        }
        l_scatter<l1, l2, p, q, m, n, W, L + 1, Lmax>(prod, acc);
    }
}

// scalar n loop (used for symmetric-diagonal columns)
template <int l1, int l2, int p, int q, int m, int BW, bool SYMIN, int Lmin, int Lmax, int n>
__device__ __forceinline__ void n_loop(float am, const float (&bcol)[2 * l2 + 1], EAcc& acc) {
    if constexpr (n < 2 * l2 + 1) {
        if constexpr (!(SYMIN && m > n) && pair_any(l1, l2, Lmin, Lmax, p, q, m, n)) {
            float prod = am * bcol[n];
            l_scatter<l1, l2, p, q, m, n, BW*((SYMIN && m < n) ? 2 : 1), Lmin, Lmax>(prod, acc);
        }
        n_loop<l1, l2, p, q, m, BW, SYMIN, Lmin, Lmax, n + 1>(am, bcol, acc);
    }
}

// paired n loop: packed FMUL2 over (2k, 2k+1); odd-d tail handled scalar
template <int l1, int l2, int p, int q, int m, int BW, int Lmin, int Lmax, int k = 0>
__device__ __forceinline__ void n_pair_loop(float am, unsigned long long am2,
                                            const float (&bcol)[2 * l2 + 1],
                                            const unsigned long long (&b2)[(2 * l2 + 1) / 2 == 0 ? 1 : (2 * l2 + 1) / 2],
                                            EAcc& acc) {
    constexpr int d2 = 2 * l2 + 1;
    if constexpr (k < d2 / 2) {
        constexpr int n0 = 2 * k, n1 = 2 * k + 1;
        constexpr bool v0 = pair_any(l1, l2, Lmin, Lmax, p, q, m, n0);
        constexpr bool v1 = pair_any(l1, l2, Lmin, Lmax, p, q, m, n1);
        if constexpr (v0 && v1) {
            unsigned long long pr = mul2(am2, b2[k]);
            float p0, p1;
            unpack2(pr, p0, p1);
            l_scatter<l1, l2, p, q, m, n0, BW, Lmin, Lmax>(p0, acc);
            l_scatter<l1, l2, p, q, m, n1, BW, Lmin, Lmax>(p1, acc);
        } else if constexpr (v0) {
            l_scatter<l1, l2, p, q, m, n0, BW, Lmin, Lmax>(am * bcol[n0], acc);
        } else if constexpr (v1) {
            l_scatter<l1, l2, p, q, m, n1, BW, Lmin, Lmax>(am * bcol[n1], acc);
        }
        n_pair_loop<l1, l2, p, q, m, BW, Lmin, Lmax, k + 1>(am, am2, bcol, b2, acc);
    } else {
        constexpr int nt = d2 - 1;  // d2 odd -> one tail element
        if constexpr (pair_any(l1, l2, Lmin, Lmax, p, q, m, nt)) {
            l_scatter<l1, l2, p, q, m, nt, BW, Lmin, Lmax>(am * bcol[nt], acc);
        }
    }
}

// m loop: load A[m,p] on demand, pack (am,am) once, run paired n loop
template <int l1, int l2, int p, int q, int BW, int Lmin, int Lmax, class MA, int m = 0>
__device__ __forceinline__ void m_loop(const MA& A, const float (&bcol)[2 * l2 + 1],
                                       const unsigned long long (&b2)[(2 * l2 + 1) / 2 == 0 ? 1 : (2 * l2 + 1) / 2],
                                       EAcc& acc) {
    constexpr int d1 = 2 * l1 + 1;
    if constexpr (m < d1) {
        if constexpr (row_any(l1, l2, Lmin, Lmax, p, q, m, 0)) {
            float am = A.template at<m * d1 + p>();
            unsigned long long am2 = pack2(am, am);
            n_pair_loop<l1, l2, p, q, m, BW, Lmin, Lmax>(am, am2, bcol, b2, acc);
        }
        m_loop<l1, l2, p, q, BW, Lmin, Lmax, MA, m + 1>(A, bcol, b2, acc);
    }
}

// diagonal column of a symmetric self term (p == q): scalar path
template <int l, int q, int Lmin, int Lmax, int m = 0>
__device__ __forceinline__ void m_loop_diag(const float (&bcol)[2 * l + 1], EAcc& acc) {
    if constexpr (m < 2 * l + 1) {
        if constexpr (row_any(l, l, Lmin, Lmax, q, q, m, m)) {
            n_loop<l, l, q, q, m, 1, true, Lmin, Lmax, m>(bcol[m], bcol, acc);
        }
        m_loop_diag<l, q, Lmin, Lmax, m + 1>(bcol, acc);
    }
}

// ----- cross term (A != B), weight BW -----

template <int l1, int l2, int BW, int Lmin, int Lmax, class MA, int q, int p = 0>
__device__ __forceinline__ void p_multi(const MA& A, const float (&bcol)[2 * l2 + 1],
                                        const unsigned long long (&b2)[(2 * l2 + 1) / 2 == 0 ? 1 : (2 * l2 + 1) / 2],
                                        EAcc& acc) {
    constexpr int d1 = 2 * l1 + 1;
    if constexpr (p < d1) {
        if constexpr (col_any_p(l1, l2, Lmin, Lmax, p, q)) {
            m_loop<l1, l2, p, q, BW, Lmin, Lmax, MA>(A, bcol, b2, acc);
        }
        p_multi<l1, l2, BW, Lmin, Lmax, MA, q, p + 1>(A, bcol, b2, acc);
    }
}

template <int l1, int l2, int BW, int Lmin, int Lmax, class MA, class MB, int q = 0>
__device__ __forceinline__ void term_multi(const MA& A, const MB& Bm, EAcc& acc) {
    constexpr int d2 = 2 * l2 + 1;
    if constexpr (q < d2) {
        if constexpr (col_any_q(l1, l2, Lmin, Lmax, q, false)) {
            float bcol[d2];
            load_col<d2, q>(Bm, bcol);
            unsigned long long b2[d2 / 2 == 0 ? 1 : d2 / 2];
            if constexpr (d2 / 2 > 0) pack_pairs<d2>(bcol, b2);
            p_multi<l1, l2, BW, Lmin, Lmax, MA, q>(A, bcol, b2, acc);
        }
        term_multi<l1, l2, BW, Lmin, Lmax, MA, MB, q + 1>(A, Bm, acc);
    }
}

// ----- symmetric self term A(x)A: p<q weight 2 full inner; p==q inner m<=n -----

template <int l, int Lmin, int Lmax, class MA, int q, int p = 0>
__device__ __forceinline__ void p_sym_multi(const MA& A, const float (&bcol)[2 * l + 1],
                                            const unsigned long long (&b2)[(2 * l + 1) / 2 == 0 ? 1 : (2 * l + 1) / 2],
                                            EAcc& acc) {
    if constexpr (p <= q) {
        if constexpr (col_any_p(l, l, Lmin, Lmax, p, q)) {
            if constexpr (p < q) {
                m_loop<l, l, p, q, 2, Lmin, Lmax, MA>(A, bcol, b2, acc);
            } else {
                m_loop_diag<l, q, Lmin, Lmax>(bcol, acc);
            }
        }
        p_sym_multi<l, Lmin, Lmax, MA, q, p + 1>(A, bcol, b2, acc);
    }
}

template <int l, int Lmin, int Lmax, class MA, int q = 0>
__device__ __forceinline__ void term_sym_multi(const MA& A, EAcc& acc) {
    constexpr int d = 2 * l + 1;
    if constexpr (q < d) {
        if constexpr (col_any_q(l, l, Lmin, Lmax, q, true)) {
            float bcol[d];
            load_col<d, q>(A, bcol);
            unsigned long long b2[d / 2 == 0 ? 1 : d / 2];
            if constexpr (d / 2 > 0) pack_pairs<d>(bcol, b2);
            p_sym_multi<l, Lmin, Lmax, MA, q>(A, bcol, b2, acc);
        }
        term_sym_multi<l, Lmin, Lmax, MA, q + 1>(A, acc);
    }
}

// ----- (0,l) degenerate term: e_l[i] += t * X_l[i] -----

template <int N, class M, int i = 0>
__device__ __forceinline__ void axpy_sm(float t, const M& X, float (&e)[N]) {
    if constexpr (i < N) {
        e[i] = __fmaf_rn(t, X.template at<i>(), e[i]);
        axpy_sm<N, M, i + 1>(t, X, e);
    }
}

// ----- L=0 contractions -----

template <int L, class MB, int ij = 0>
__device__ __forceinline__ void invar_mat(const float (&A)[(2 * L + 1) * (2 * L + 1)],
                                          const MB& Bm, float& s) {
    constexpr int D = 2 * L + 1;
    if constexpr (ij < D * D) {
        constexpr int i = ij / D, j = ij % D;
        constexpr float w = (((i + j) & 1) ? -1.0f : 1.0f) / (float)D;
        s = __fmaf_rn(w, A[ij] * Bm.template at<(D - 1 - i) * D + (D - 1 - j)>(), s);
        invar_mat<L, MB, ij + 1>(A, Bm, s);
    }
}

template <int L, int ij = 0>
__device__ __forceinline__ void invar_self(const float (&A)[(2 * L + 1) * (2 * L + 1)],
                                           float& s) {
    constexpr int D = 2 * L + 1, DD = D * D;
    if constexpr (ij <= (DD - 1) / 2) {
        constexpr int i = ij / D, j = ij % D;
        constexpr float base = (ij == DD - 1 - ij) ? 1.0f : 2.0f;
        constexpr float w = (((i + j) & 1) ? -base : base) / (float)D;
        s = __fmaf_rn(w, A[ij] * A[DD - 1 - ij], s);
        invar_self<L, ij + 1>(A, s);
    }
}

// ---------------------------------------------------------------------------
// Kernel: one thread per batch element, four passes (peak live <= ~90 regs):
//  A1: even terms L{0,1}; A2: even terms L{2,3}; B1: odd L{1}; B2: odd L{2,3}.
// Products via packed f32x2 FMUL2 where pairs are valid. 5 CTAs/SM @ 96 regs.
// ---------------------------------------------------------------------------

constexpr int O0 = 0, O1 = 128, O2 = 1280, O3 = 4480, SM_FLOATS = 10752;  // 84*128

__global__ void __launch_bounds__(128, 5)
wigner_kernel(const float* __restrict__ gx0, const float* __restrict__ gx1,
              const float* __restrict__ gx2, const float* __restrict__ gx3,
              float* __restrict__ out, int n) {
    __shared__ float sm[SM_FLOATS];
    const int tid = threadIdx.x;
    const int base = blockIdx.x * 128;

    if (base + 128 <= n) {  // full CTA: vectorized linear copy
        const float4* g0 = (const float4*)(gx0 + (size_t)base);
        const float4* g1 = (const float4*)(gx1 + (size_t)base * 9);
        const float4* g2 = (const float4*)(gx2 + (size_t)base * 25);
        const float4* g3 = (const float4*)(gx3 + (size_t)base * 49);
        float4* s = (float4*)sm;
        if (tid < 32) s[tid] = g0[tid];
#pragma unroll
        for (int i = tid; i < 288; i += 128) s[32 + i] = g1[i];
#pragma unroll
        for (int i = tid; i < 800; i += 128) s[320 + i] = g2[i];
#pragma unroll
        for (int i = tid; i < 1568; i += 128) s[1120 + i] = g3[i];
    } else {  // tail CTA: scalar with bounds
        const int c = n - base;
        for (int i = tid; i < 128; i += 128) sm[O0 + i] = (i < c) ? gx0[base + i] : 0.f;
        for (int i = tid; i < 1152; i += 128) sm[O1 + i] = (i < c * 9) ? gx1[base * 9 + i] : 0.f;
        for (int i = tid; i < 3200; i += 128) sm[O2 + i] = (i < c * 25) ? gx2[base * 25 + i] : 0.f;
        for (int i = tid; i < 6272; i += 128) sm[O3 + i] = (i < c * 49) ? gx3[base * 49 + i] : 0.f;
    }
    __syncthreads();

    const int b = base + tid;
    const bool valid = (b < n);

    const SmemMat S1{sm + O1 + tid * 9};
    const SmemMat S2{sm + O2 + tid * 25};
    const SmemMat S3{sm + O3 + tid * 49};

    float out2, out3;

    {  // ----- Pass A1: even terms, L in {0,1} -> e0, e1 -----
        EAcc a;
        zeroa(a.e0); zeroa(a.e1);
        const float X0 = sm[O0 + tid];
        a.e0[0] = X0 * X0;                     // (0,0) -> L=0
        term_sym_multi<1, 0, 1>(S1, a);        // (1,1) -> L=0,1
        term_sym_multi<2, 0, 1>(S2, a);        // (2,2) -> L=0,1
        term_sym_multi<3, 0, 1>(S3, a);        // (3,3) -> L=0,1
        out2 = a.e0[0] * X0;
        out3 = a.e0[0] * a.e0[0];
        invar_self<1>(a.e1, out3);             // (1,-)
        if (valid) {
            out[b * 4 + 0] = X0;
            out[b * 4 + 1] = a.e0[0];
        }
    }
    __syncthreads();
    {  // ----- Pass A2: even terms, L in {2,3} -> e2, e3 -----
        EAcc a;
        zeroa(a.e2); zeroa(a.e3);
        term_sym_multi<1, 2, 2>(S1, a);        // (1,1) -> L=2
        term_sym_multi<2, 2, 3>(S2, a);        // (2,2) -> L=2,3
        term_sym_multi<3, 2, 3>(S3, a);        // (3,3) -> L=2,3
        term_multi<1, 3, 2, 2, 3>(S1, S3, a);  // (1,3)x2 -> L=2,3
        const float X0 = sm[O0 + tid];
        axpy_sm<25>(X0 + X0, S2, a.e2);        // (0,2)x2 -> L=2
        invar_mat<2>(a.e2, S2, out2);          // (2,+) x X2
        invar_self<2>(a.e2, out3);
        invar_self<3>(a.e3, out3);             // (3,-)
    }
    __syncthreads();
    {  // ----- Pass B1: odd terms, L = 1 -> e1 -----
        EAcc a;
        zeroa(a.e1);
        const float X0 = sm[O0 + tid];
        axpy_sm<9>(X0 + X0, S1, a.e1);         // (0,1)x2 -> L=1
        term_multi<1, 2, 2, 1, 1>(S1, S2, a);  // (1,2)x2 -> L=1
        term_multi<2, 3, 2, 1, 1>(S2, S3, a);  // (2,3)x2 -> L=1
        invar_mat<1>(a.e1, S1, out2);          // (1,+) x X1
        invar_self<1>(a.e1, out3);
    }
    __syncthreads();
    {  // ----- Pass B2: odd terms, L in {2,3} -> e2, e3 -----
        EAcc a;
        zeroa(a.e2); zeroa(a.e3);
        term_multi<1, 2, 2, 2, 3>(S1, S2, a);  // (1,2)x2 -> L=2,3
        term_multi<2, 3, 2, 2, 3>(S2, S3, a);  // (2,3)x2 -> L=2,3
        const float X0 = sm[O0 + tid];
        axpy_sm<49>(X0 + X0, S3, a.e3);        // (0,3)x2 -> L=3
        invar_self<2>(a.e2, out3);             // (2,-)
        invar_mat<3>(a.e3, S3, out2);          // (3,+) x X3
        invar_self<3>(a.e3, out3);
    }

    if (valid) {
        out[b * 4 + 2] = out2;
        out[b * 4 + 3] = out3;
    }
}

// ---------------------------------------------------------------------------
// Harness entry point
// ---------------------------------------------------------------------------

extern "C" void kernel_launch(void* const* d_in, const int* in_sizes, int n_in,
                              void* d_out, int out_size) {
    const float* x0 = (const float*)d_in[0];
    const float* x1 = (const float*)d_in[1];
    const float* x2 = (const float*)d_in[2];
    const float* x3 = (const float*)d_in[3];
    float* out = (float*)d_out;

    static bool attr_set = false;
    if (!attr_set) {
        cudaFuncSetAttribute(wigner_kernel,
                             cudaFuncAttributePreferredSharedMemoryCarveout, 100);
        attr_set = true;
    }

    const int n = in_sizes[0];  // B
    const int grid = (n + 127) / 128;
    wigner_kernel<<<grid, 128>>>(x0, x1, x2, x3, out, n);
}

// round 10
// speedup vs baseline: 1.0025x; 1.0025x over previous
#include <cuda_runtime.h>

// ---------------------------------------------------------------------------
// Compile-time Clebsch-Gordan coefficients (Racah formula), matching numpy ref.
// ---------------------------------------------------------------------------

__host__ __device__ constexpr double cfact(int n) {
    double r = 1.0;
    for (int i = 2; i <= n; ++i) r *= (double)i;
    return r;
}

__host__ __device__ constexpr double csqrt_(double x) {
    if (x <= 0.0) return 0.0;
    double g = x > 1.0 ? x : 1.0;
    for (int i = 0; i < 100; ++i) g = 0.5 * (g + x / g);
    return g;
}

__host__ __device__ constexpr double cg_elem(int l1, int l2, int L, int m1, int m2) {
    const int M = m1 + m2;
    if (M < -L || M > L) return 0.0;
    const double pref0 = csqrt_((2.0 * L + 1.0) * cfact(L + l1 - l2) * cfact(L - l1 + l2) *
                                cfact(l1 + l2 - L) / cfact(l1 + l2 + L + 1));
    const double pref = pref0 * csqrt_(cfact(L + M) * cfact(L - M) * cfact(l1 - m1) *
                                       cfact(l1 + m1) * cfact(l2 - m2) * cfact(l2 + m2));
    double s = 0.0;
    for (int k = 0; k <= l1 + l2 - L; ++k) {
        if (l1 - m1 - k < 0 || l2 + m2 - k < 0 || L - l2 + m1 + k < 0 || L - l1 - m2 + k < 0)
            continue;
        const double d = cfact(k) * cfact(l1 + l2 - L - k) * cfact(l1 - m1 - k) *
                         cfact(l2 + m2 - k) * cfact(L - l2 + m1 + k) * cfact(L - l1 - m2 + k);
        s += ((k & 1) ? -1.0 : 1.0) / d;
    }
    return pref * s;
}

__host__ __device__ constexpr bool cg_nz(double c) { return c > 1e-12 || c < -1e-12; }

__host__ __device__ constexpr bool okL(int l1, int l2, int L, int a, int b) {
    const int off = l1 + l2 - L;
    const int mu = a + b - off;
    return mu >= 0 && mu <= 2 * L && cg_nz(cg_elem(l1, l2, L, a - l1, b - l2));
}

__host__ __device__ constexpr bool pair_any(int l1, int l2, int Lmin, int Lmax,
                                            int p, int q, int m, int n) {
    for (int L = Lmin; L <= Lmax; ++L)
        if (okL(l1, l2, L, m, n) && okL(l1, l2, L, p, q)) return true;
    return false;
}

__host__ __device__ constexpr bool col_any_p(int l1, int l2, int Lmin, int Lmax, int p, int q) {
    for (int L = Lmin; L <= Lmax; ++L)
        if (okL(l1, l2, L, p, q)) return true;
    return false;
}

__host__ __device__ constexpr bool col_any_q(int l1, int l2, int Lmin, int Lmax, int q, bool sym) {
    const int pmax = sym ? q : 2 * l1;
    for (int p = 0; p <= pmax; ++p)
        if (col_any_p(l1, l2, Lmin, Lmax, p, q)) return true;
    return false;
}

__host__ __device__ constexpr bool row_any(int l1, int l2, int Lmin, int Lmax,
                                           int p, int q, int m, int nlo) {
    for (int nn = nlo; nn <= 2 * l2; ++nn)
        if (pair_any(l1, l2, Lmin, Lmax, p, q, m, nn)) return true;
    return false;
}

// ---------------------------------------------------------------------------
// Packed f32x2 helpers (sm_100+): FMUL2 does 2 products per instruction.
// ---------------------------------------------------------------------------

__device__ __forceinline__ unsigned long long pack2(float lo, float hi) {
    unsigned long long r;
    asm("mov.b64 %0, {%1, %2};" : "=l"(r) : "f"(lo), "f"(hi));
    return r;
}

__device__ __forceinline__ unsigned long long mul2(unsigned long long a, unsigned long long b) {
    unsigned long long r;
    asm("mul.rn.f32x2 %0, %1, %2;" : "=l"(r) : "l"(a), "l"(b));
    return r;
}

__device__ __forceinline__ void unpack2(unsigned long long v, float& lo, float& hi) {
    asm("mov.b64 {%0, %1}, %2;" : "=f"(lo), "=f"(hi) : "l"(v));
}

// ---------------------------------------------------------------------------
// Smem operand wrapper (linear layout: this thread's matrix at p[0..d*d)).
// ---------------------------------------------------------------------------

struct SmemMat {
    const float* p;
    template <int I> __device__ __forceinline__ float at() const { return p[I]; }
};

// Packed column: d/2 f32x2 pairs + scalar tail (d odd). Exactly d registers —
// same footprint as a scalar float[d] column (this parity is load-bearing:
// round 9 kept both forms live and spilled).
template <int d>
struct PCol {
    unsigned long long pr[d / 2];
    float tail;
    template <int n> __device__ __forceinline__ float get() const {
        if constexpr ((d & 1) && n == d - 1) {
            return tail;
        } else {
            float lo, hi;
            unpack2(pr[n / 2], lo, hi);
            return (n & 1) ? hi : lo;
        }
    }
};

template <int d, int col, class M, int k = 0>
__device__ __forceinline__ void load_col_packed(const M& mat, PCol<d>& dst) {
    if constexpr (k < d / 2) {
        float lo = mat.template at<(2 * k) * d + col>();
        float hi = mat.template at<(2 * k + 1) * d + col>();
        dst.pr[k] = pack2(lo, hi);
        load_col_packed<d, col, M, k + 1>(mat, dst);
    } else if constexpr (d & 1) {
        dst.tail = mat.template at<(d - 1) * d + col>();
    }
}

// ---------------------------------------------------------------------------
// Accumulator group (each pass touches only a subset; SROA drops the rest)
// ---------------------------------------------------------------------------

struct EAcc {
    float e0[1];
    float e1[9];
    float e2[25];
    float e3[49];
};

template <int L> __device__ __forceinline__ auto& getE(EAcc& a) {
    if constexpr (L == 0) return a.e0;
    else if constexpr (L == 1) return a.e1;
    else if constexpr (L == 2) return a.e2;
    else return a.e3;
}

template <int N>
__device__ __forceinline__ void zeroa(float (&e)[N]) {
#pragma unroll
    for (int i = 0; i < N; ++i) e[i] = 0.f;
}

// ---------------------------------------------------------------------------
// CG scatter: one product feeds an FFMA-imm per valid L.
// ---------------------------------------------------------------------------

template <int l1, int l2, int p, int q, int m, int n, int W, int L, int Lmax>
__device__ __forceinline__ void l_scatter(float prod, EAcc& acc) {
    if constexpr (L <= Lmax) {
        if constexpr (okL(l1, l2, L, m, n) && okL(l1, l2, L, p, q)) {
            constexpr int off = l1 + l2 - L, DL = 2 * L + 1;
            constexpr int mu = m + n - off, nu = p + q - off;
            constexpr float w = (float)((double)W * cg_elem(l1, l2, L, m - l1, n - l2) *
                                        cg_elem(l1, l2, L, p - l1, q - l2));
            getE<L>(acc)[mu * DL + nu] = __fmaf_rn(w, prod, getE<L>(acc)[mu * DL + nu]);
        }
        l_scatter<l1, l2, p, q, m, n, W, L + 1, Lmax>(prod, acc);
    }
}

// scalar n loop (symmetric-diagonal columns): extracts scalars from PCol
template <int l1, int l2, int p, int q, int m, int BW, bool SYMIN, int Lmin, int Lmax, int n>
__device__ __forceinline__ void n_loop(float am, const PCol<2 * l2 + 1>& bc, EAcc& acc) {
    if constexpr (n < 2 * l2 + 1) {
        if constexpr (!(SYMIN && m > n) && pair_any(l1, l2, Lmin, Lmax, p, q, m, n)) {
            float prod = am * bc.template get<n>();
            l_scatter<l1, l2, p, q, m, n, BW*((SYMIN && m < n) ? 2 : 1), Lmin, Lmax>(prod, acc);
        }
        n_loop<l1, l2, p, q, m, BW, SYMIN, Lmin, Lmax, n + 1>(am, bc, acc);
    }
}

// paired n loop: FMUL2 where both lanes valid; scalar fallback otherwise
template <int l1, int l2, int p, int q, int m, int BW, int Lmin, int Lmax, int k = 0>
__device__ __forceinline__ void n_pair_loop(float am, unsigned long long am2,
                                            const PCol<2 * l2 + 1>& bc, EAcc& acc) {
    constexpr int d2 = 2 * l2 + 1;
    if constexpr (k < d2 / 2) {
        constexpr int n0 = 2 * k, n1 = 2 * k + 1;
        constexpr bool v0 = pair_any(l1, l2, Lmin, Lmax, p, q, m, n0);
        constexpr bool v1 = pair_any(l1, l2, Lmin, Lmax, p, q, m, n1);
        if constexpr (v0 && v1) {
            unsigned long long prv = mul2(am2, bc.pr[k]);
            float p0, p1;
            unpack2(prv, p0, p1);
            l_scatter<l1, l2, p, q, m, n0, BW, Lmin, Lmax>(p0, acc);
            l_scatter<l1, l2, p, q, m, n1, BW, Lmin, Lmax>(p1, acc);
        } else if constexpr (v0) {
            l_scatter<l1, l2, p, q, m, n0, BW, Lmin, Lmax>(am * bc.template get<n0>(), acc);
        } else if constexpr (v1) {
            l_scatter<l1, l2, p, q, m, n1, BW, Lmin, Lmax>(am * bc.template get<n1>(), acc);
        }
        n_pair_loop<l1, l2, p, q, m, BW, Lmin, Lmax, k + 1>(am, am2, bc, acc);
    } else if constexpr (d2 & 1) {
        constexpr int nt = d2 - 1;
        if constexpr (pair_any(l1, l2, Lmin, Lmax, p, q, m, nt)) {
            l_scatter<l1, l2, p, q, m, nt, BW, Lmin, Lmax>(am * bc.tail, acc);
        }
    }
}

// m loop: load A[m,p] on demand, replicate into a pair, run paired n loop
template <int l1, int l2, int p, int q, int BW, int Lmin, int Lmax, class MA, int m = 0>
__device__ __forceinline__ void m_loop(const MA& A, const PCol<2 * l2 + 1>& bc, EAcc& acc) {
    constexpr int d1 = 2 * l1 + 1;
    if constexpr (m < d1) {
        if constexpr (row_any(l1, l2, Lmin, Lmax, p, q, m, 0)) {
            float am = A.template at<m * d1 + p>();
            unsigned long long am2 = pack2(am, am);
            n_pair_loop<l1, l2, p, q, m, BW, Lmin, Lmax>(am, am2, bc, acc);
        }
        m_loop<l1, l2, p, q, BW, Lmin, Lmax, MA, m + 1>(A, bc, acc);
    }
}

// diagonal column of a symmetric self term (p == q): scalar path
template <int l, int q, int Lmin, int Lmax, int m = 0>
__device__ __forceinline__ void m_loop_diag(const PCol<2 * l + 1>& bc, EAcc& acc) {
    if constexpr (m < 2 * l + 1) {
        if constexpr (row_any(l, l, Lmin, Lmax, q, q, m, m)) {
            n_loop<l, l, q, q, m, 1, true, Lmin, Lmax, m>(bc.template get<m>(), bc, acc);
        }
        m_loop_diag<l, q, Lmin, Lmax, m + 1>(bc, acc);
    }
}

// ----- cross term (A != B), weight BW -----

template <int l1, int l2, int BW, int Lmin, int Lmax, class MA, int q, int p = 0>
__device__ __forceinline__ void p_multi(const MA& A, const PCol<2 * l2 + 1>& bc, EAcc& acc) {
    constexpr int d1 = 2 * l1 + 1;
    if constexpr (p < d1) {
        if constexpr (col_any_p(l1, l2, Lmin, Lmax, p, q)) {
            m_loop<l1, l2, p, q, BW, Lmin, Lmax, MA>(A, bc, acc);
        }
        p_multi<l1, l2, BW, Lmin, Lmax, MA, q, p + 1>(A, bc, acc);
    }
}

template <int l1, int l2, int BW, int Lmin, int Lmax, class MA, class MB, int q = 0>
__device__ __forceinline__ void term_multi(const MA& A, const MB& Bm, EAcc& acc) {
    constexpr int d2 = 2 * l2 + 1;
    if constexpr (q < d2) {
        if constexpr (col_any_q(l1, l2, Lmin, Lmax, q, false)) {
            PCol<d2> bc;
            load_col_packed<d2, q>(Bm, bc);
            p_multi<l1, l2, BW, Lmin, Lmax, MA, q>(A, bc, acc);
        }
        term_multi<l1, l2, BW, Lmin, Lmax, MA, MB, q + 1>(A, Bm, acc);
    }
}

// ----- symmetric self term A(x)A: p<q weight 2 full inner; p==q inner m<=n -----

template <int l, int Lmin, int Lmax, class MA, int q, int p = 0>
__device__ __forceinline__ void p_sym_multi(const MA& A, const PCol<2 * l + 1>& bc, EAcc& acc) {
    if constexpr (p <= q) {
        if constexpr (col_any_p(l, l, Lmin, Lmax, p, q)) {
            if constexpr (p < q) {
                m_loop<l, l, p, q, 2, Lmin, Lmax, MA>(A, bc, acc);
            } else {
                m_loop_diag<l, q, Lmin, Lmax>(bc, acc);
            }
        }
        p_sym_multi<l, Lmin, Lmax, MA, q, p + 1>(A, bc, acc);
    }
}

template <int l, int Lmin, int Lmax, class MA, int q = 0>
__device__ __forceinline__ void term_sym_multi(const MA& A, EAcc& acc) {
    constexpr int d = 2 * l + 1;
    if constexpr (q < d) {
        if constexpr (col_any_q(l, l, Lmin, Lmax, q, true)) {
            PCol<d> bc;
            load_col_packed<d, q>(A, bc);
            p_sym_multi<l, Lmin, Lmax, MA, q>(A, bc, acc);
        }
        term_sym_multi<l, Lmin, Lmax, MA, q + 1>(A, acc);
    }
}

// ----- (0,l) degenerate term: e_l[i] += t * X_l[i] -----

template <int N, class M, int i = 0>
__device__ __forceinline__ void axpy_sm(float t, const M& X, float (&e)[N]) {
    if constexpr (i < N) {
        e[i] = __fmaf_rn(t, X.template at<i>(), e[i]);
        axpy_sm<N, M, i + 1>(t, X, e);
    }
}

// ----- L=0 contractions -----

template <int L, class MB, int ij = 0>
__device__ __forceinline__ void invar_mat(const float (&A)[(2 * L + 1) * (2 * L + 1)],
                                          const MB& Bm, float& s) {
    constexpr int D = 2 * L + 1;
    if constexpr (ij < D * D) {
        constexpr int i = ij / D, j = ij % D;
        constexpr float w = (((i + j) & 1) ? -1.0f : 1.0f) / (float)D;
        s = __fmaf_rn(w, A[ij] * Bm.template at<(D - 1 - i) * D + (D - 1 - j)>(), s);
        invar_mat<L, MB, ij + 1>(A, Bm, s);
    }
}

template <int L, int ij = 0>
__device__ __forceinline__ void invar_self(const float (&A)[(2 * L + 1) * (2 * L + 1)],
                                           float& s) {
    constexpr int D = 2 * L + 1, DD = D * D;
    if constexpr (ij <= (DD - 1) / 2) {
        constexpr int i = ij / D, j = ij % D;
        constexpr float base = (ij == DD - 1 - ij) ? 1.0f : 2.0f;
        constexpr float w = (((i + j) & 1) ? -base : base) / (float)D;
        s = __fmaf_rn(w, A[ij] * A[DD - 1 - ij], s);
        invar_self<L, ij + 1>(A, s);
    }
}

// ---------------------------------------------------------------------------
// Kernel: one thread per batch element, four passes (peak live <= ~90 regs):
//  A1: even terms L{0,1}; A2: even terms L{2,3}; B1: odd L{1}; B2: odd L{2,3}.
// Products via FMUL2 on packed column pairs. 5 CTAs/SM @ 96 regs.
// ---------------------------------------------------------------------------

constexpr int O0 = 0, O1 = 128, O2 = 1280, O3 = 4480, SM_FLOATS = 10752;  // 84*128

__global__ void __launch_bounds__(128, 5)
wigner_kernel(const float* __restrict__ gx0, const float* __restrict__ gx1,
              const float* __restrict__ gx2, const float* __restrict__ gx3,
              float* __restrict__ out, int n) {
    __shared__ float sm[SM_FLOATS];
    const int tid = threadIdx.x;
    const int base = blockIdx.x * 128;

    if (base + 128 <= n) {  // full CTA: vectorized linear copy
        const float4* g0 = (const float4*)(gx0 + (size_t)base);
        const float4* g1 = (const float4*)(gx1 + (size_t)base * 9);
        const float4* g2 = (const float4*)(gx2 + (size_t)base * 25);
        const float4* g3 = (const float4*)(gx3 + (size_t)base * 49);
        float4* s = (float4*)sm;
        if (tid < 32) s[tid] = g0[tid];
#pragma unroll
        for (int i = tid; i < 288; i += 128) s[32 + i] = g1[i];
#pragma unroll
        for (int i = tid; i < 800; i += 128) s[320 + i] = g2[i];
#pragma unroll
        for (int i = tid; i < 1568; i += 128) s[1120 + i] = g3[i];
    } else {  // tail CTA: scalar with bounds
        const int c = n - base;
        for (int i = tid; i < 128; i += 128) sm[O0 + i] = (i < c) ? gx0[base + i] : 0.f;
        for (int i = tid; i < 1152; i += 128) sm[O1 + i] = (i < c * 9) ? gx1[base * 9 + i] : 0.f;
        for (int i = tid; i < 3200; i += 128) sm[O2 + i] = (i < c * 25) ? gx2[base * 25 + i] : 0.f;
        for (int i = tid; i < 6272; i += 128) sm[O3 + i] = (i < c * 49) ? gx3[base * 49 + i] : 0.f;
    }
    __syncthreads();

    const int b = base + tid;
    const bool valid = (b < n);

    const SmemMat S1{sm + O1 + tid * 9};
    const SmemMat S2{sm + O2 + tid * 25};
    const SmemMat S3{sm + O3 + tid * 49};

    float out2, out3;

    {  // ----- Pass A1: even terms, L in {0,1} -> e0, e1 -----
        EAcc a;
        zeroa(a.e0); zeroa(a.e1);
        const float X0 = sm[O0 + tid];
        a.e0[0] = X0 * X0;                     // (0,0) -> L=0
        term_sym_multi<1, 0, 1>(S1, a);        // (1,1) -> L=0,1
        term_sym_multi<2, 0, 1>(S2, a);        // (2,2) -> L=0,1
        term_sym_multi<3, 0, 1>(S3, a);        // (3,3) -> L=0,1
        out2 = a.e0[0] * X0;
        out3 = a.e0[0] * a.e0[0];
        invar_self<1>(a.e1, out3);             // (1,-)
        if (valid) {
            out[b * 4 + 0] = X0;
            out[b * 4 + 1] = a.e0[0];
        }
    }
    __syncthreads();
    {  // ----- Pass A2: even terms, L in {2,3} -> e2, e3 -----
        EAcc a;
        zeroa(a.e2); zeroa(a.e3);
        term_sym_multi<1, 2, 2>(S1, a);        // (1,1) -> L=2
        term_sym_multi<2, 2, 3>(S2, a);        // (2,2) -> L=2,3
        term_sym_multi<3, 2, 3>(S3, a);        // (3,3) -> L=2,3
        term_multi<1, 3, 2, 2, 3>(S1, S3, a);  // (1,3)x2 -> L=2,3
        const float X0 = sm[O0 + tid];
        axpy_sm<25>(X0 + X0, S2, a.e2);        // (0,2)x2 -> L=2
        invar_mat<2>(a.e2, S2, out2);          // (2,+) x X2
        invar_self<2>(a.e2, out3);
        invar_self<3>(a.e3, out3);             // (3,-)
    }
    __syncthreads();
    {  // ----- Pass B1: odd terms, L = 1 -> e1 -----
        EAcc a;
        zeroa(a.e1);
        const float X0 = sm[O0 + tid];
        axpy_sm<9>(X0 + X0, S1, a.e1);         // (0,1)x2 -> L=1
        term_multi<1, 2, 2, 1, 1>(S1, S2, a);  // (1,2)x2 -> L=1
        term_multi<2, 3, 2, 1, 1>(S2, S3, a);  // (2,3)x2 -> L=1
        invar_mat<1>(a.e1, S1, out2);          // (1,+) x X1
        invar_self<1>(a.e1, out3);
    }
    __syncthreads();
    {  // ----- Pass B2: odd terms, L in {2,3} -> e2, e3 -----
        EAcc a;
        zeroa(a.e2); zeroa(a.e3);
        term_multi<1, 2, 2, 2, 3>(S1, S2, a);  // (1,2)x2 -> L=2,3
        term_multi<2, 3, 2, 2, 3>(S2, S3, a);  // (2,3)x2 -> L=2,3
        const float X0 = sm[O0 + tid];
        axpy_sm<49>(X0 + X0, S3, a.e3);        // (0,3)x2 -> L=3
        invar_self<2>(a.e2, out3);             // (2,-)
        invar_mat<3>(a.e3, S3, out2);          // (3,+) x X3
        invar_self<3>(a.e3, out3);
    }

    if (valid) {
        out[b * 4 + 2] = out2;
        out[b * 4 + 3] = out3;
    }
}

// ---------------------------------------------------------------------------
// Harness entry point
// ---------------------------------------------------------------------------

extern "C" void kernel_launch(void* const* d_in, const int* in_sizes, int n_in,
                              void* d_out, int out_size) {
    const float* x0 = (const float*)d_in[0];
    const float* x1 = (const float*)d_in[1];
    const float* x2 = (const float*)d_in[2];
    const float* x3 = (const float*)d_in[3];
    float* out = (float*)d_out;

    static bool attr_set = false;
    if (!attr_set) {
        cudaFuncSetAttribute(wigner_kernel,
                             cudaFuncAttributePreferredSharedMemoryCarveout, 100);
        attr_set = true;
    }

    const int n = in_sizes[0];  // B
    const int grid = (n + 127) / 128;
    wigner_kernel<<<grid, 128>>>(x0, x1, x2, x3, out, n);
}